// round 15
// baseline (speedup 1.0000x reference)
#include <cuda_runtime.h>
#include <cuda_bf16.h>
#include <cstdint>

#define EPSQ 1e-8f
static const int BATCH = 16;
static const int NI = 15488;

// ---------------- scratch ----------------
__device__ __nv_bfloat16 g_c1b[(size_t)50176 * 256];
__device__ __nv_bfloat16 g_c2b[(size_t)43264 * 256];
__device__ __nv_bfloat16 g_partb[(size_t)12 * 7744 * 256]; // bf16 split-K partials (conv2 uses 2*43264*256)
__device__ float g_p [(size_t)16 * 256 * 22 * 22];
__device__ float g_u [(size_t)16 * 15488 * 8];
__device__ __nv_bfloat16 g_uhatb[(size_t)16 * 15488 * 10 * 16];
__device__ __nv_bfloat16 g_w1b[(size_t)2 * 16384];
__device__ __nv_bfloat16 g_w2b[(size_t)200 * 8192];
__device__ __nv_bfloat16 g_wpb[(size_t)648 * 8192];
__device__ float g_s[16 * 160];
__device__ float g_V[16 * 160];
__device__ float g_masked[16 * 160];
__device__ float g_d1[16 * 512];
__device__ float g_d2[16 * 1024];

// ---------------- helpers ----------------
__device__ __forceinline__ uint32_t smem_to_u32(const void* p) {
    uint32_t a;
    asm("{ .reg .u64 t; cvta.to.shared.u64 t, %1; cvt.u32.u64 %0, t; }" : "=r"(a) : "l"(p));
    return a;
}
__device__ __forceinline__ void ldsm_x4(uint32_t& r0, uint32_t& r1, uint32_t& r2, uint32_t& r3, uint32_t addr) {
    asm volatile("ldmatrix.sync.aligned.m8n8.x4.shared.b16 {%0,%1,%2,%3}, [%4];"
                 : "=r"(r0), "=r"(r1), "=r"(r2), "=r"(r3) : "r"(addr));
}
__device__ __forceinline__ void ldsm_x4_t(uint32_t& r0, uint32_t& r1, uint32_t& r2, uint32_t& r3, uint32_t addr) {
    asm volatile("ldmatrix.sync.aligned.m8n8.x4.trans.shared.b16 {%0,%1,%2,%3}, [%4];"
                 : "=r"(r0), "=r"(r1), "=r"(r2), "=r"(r3) : "r"(addr));
}
__device__ __forceinline__ void mma16816(float* c, const uint32_t* a, const uint32_t* b) {
    asm volatile("mma.sync.aligned.m16n8k16.row.col.f32.bf16.bf16.f32 "
                 "{%0,%1,%2,%3}, {%4,%5,%6,%7}, {%8,%9}, {%0,%1,%2,%3};"
                 : "+f"(c[0]), "+f"(c[1]), "+f"(c[2]), "+f"(c[3])
                 : "r"(a[0]), "r"(a[1]), "r"(a[2]), "r"(a[3]), "r"(b[0]), "r"(b[1]));
}
#define CP_ASYNC16(dst, src, sz) \
    asm volatile("cp.async.cg.shared.global [%0], [%1], 16, %2;" :: "r"(dst), "l"(src), "r"(sz))
#define CP_COMMIT() asm volatile("cp.async.commit_group;" ::: "memory")
#define CP_WAIT(n)  asm volatile("cp.async.wait_group %0;" :: "n"(n) : "memory")

__device__ __forceinline__ float bf_lo(uint32_t u) {
    return __bfloat162float(__ushort_as_bfloat16((unsigned short)(u & 0xffff)));
}
__device__ __forceinline__ float bf_hi(uint32_t u) {
    return __bfloat162float(__ushort_as_bfloat16((unsigned short)(u >> 16)));
}
__device__ __forceinline__ uint32_t bf_pack(float a, float b) {
    return ((uint32_t)__bfloat16_as_ushort(__float2bfloat16(b)) << 16)
         | __bfloat16_as_ushort(__float2bfloat16(a));
}

// ---------------- weight transforms ----------------
__global__ void transform_w_kernel(const float* __restrict__ w,
                                   __nv_bfloat16* __restrict__ wb,
                                   int KH, int KW, int NCHUNK) {
    int idx = blockIdx.x * 256 + threadIdx.x;
    int total = NCHUNK * 2 * 64 * 64;
    if (idx >= total) return;
    int np = idx & 63;
    int k  = (idx >> 6) & 63;
    int ntile = (idx >> 12) & 1;
    int chunk = idx >> 13;
    int kyx = chunk >> 2;
    int ic = (chunk & 3) * 64 + k;
    int ky = kyx / KW, kx = kyx % KW;
    int oc = ntile * 128 + np * 2;
    size_t KHW = (size_t)KH * KW;
    size_t wi = (((size_t)oc * 256 + ic) * KH + ky) * KW + kx;
    uint32_t pk = bf_pack(w[wi], w[wi + 256 * KHW]);
    int off = k * 256 + np * 4;
    int sw = off ^ ((k & 7) << 4);
    *(uint32_t*)((char*)wb + (size_t)(chunk * 2 + ntile) * 16384 + sw) = pk;
}

__global__ void transform_w1_kernel(const float* __restrict__ w,
                                    __nv_bfloat16* __restrict__ wb) {
    int idx = blockIdx.x * 256 + threadIdx.x;
    if (idx >= 2 * 64 * 128) return;
    int np = idx & 127;
    int k  = (idx >> 7) & 63;
    int chunk = idx >> 13;
    int kk = chunk * 64 + k;
    int oc = np * 2;
    float f0 = (kk < 81) ? w[(size_t)oc * 81 + kk] : 0.f;
    float f1 = (kk < 81) ? w[(size_t)(oc + 1) * 81 + kk] : 0.f;
    int off = k * 512 + np * 4;
    int sw = off ^ ((k & 7) << 4);
    *(uint32_t*)((char*)wb + (size_t)chunk * 32768 + sw) = bf_pack(f0, f1);
}

// ---------------- conv1 via HMMA (unchanged) ----------------
#define C1_STG 49152
#define C1_SMEM (2 * C1_STG)

__global__ __launch_bounds__(512, 1)
void conv1_mma_kernel(const float* __restrict__ x,
                      const __nv_bfloat16* __restrict__ wb,
                      const float* __restrict__ bias,
                      __nv_bfloat16* __restrict__ ob16) {
    extern __shared__ char smem[];
    const uint32_t sb = smem_to_u32(smem);
    const int tid = threadIdx.x;
    const int wid = tid >> 5, lid = tid & 31;
    const int tile = blockIdx.x;

    const int r = tid >> 2, sp = tid & 3;
    const int p_mine = tile * 128 + r;
    const bool pvalid = p_mine < 50176;
    int pb = 0, pr = 0, pcx = 0;
    if (pvalid) {
        pb = p_mine / 3136;
        int rem = p_mine - pb * 3136;
        pr = rem / 56;
        pcx = rem - pr * 56;
    }

    const int wm = wid >> 2, wn = wid & 3;
    const int lane15 = lid & 15, lane16 = lid >> 4;
    const int gid = lid >> 2, tig = lid & 3;

    float acc[2][8][4];
    #pragma unroll
    for (int ma = 0; ma < 2; ma++)
        #pragma unroll
        for (int na = 0; na < 8; na++)
            #pragma unroll
            for (int q = 0; q < 4; q++) acc[ma][na][q] = 0.f;

    #pragma unroll
    for (int c = 0; c < 2; c++) {
        uint32_t s0 = sb + c * C1_STG;
        const char* bsrc = (const char*)(wb + (size_t)c * 16384);
        #pragma unroll
        for (int i = 0; i < 4; i++) {
            uint32_t u = (tid + i * 512) * 16;
            CP_ASYNC16(s0 + 16384 + u, bsrc + u, 16);
        }
        const float* xb = x + (size_t)pb * 4096;
        #pragma unroll
        for (int t = 0; t < 8; t++) {
            int k0 = c * 64 + sp * 16 + 2 * t;
            float v0 = 0.f, v1 = 0.f;
            if (pvalid && k0 < 81) {
                int ky = k0 / 9, kx = k0 - 9 * ky;
                v0 = xb[(pr + ky) * 64 + pcx + kx];
            }
            if (pvalid && k0 + 1 < 81) {
                int ky = (k0 + 1) / 9, kx = (k0 + 1) - 9 * ky;
                v1 = xb[(pr + ky) * 64 + pcx + kx];
            }
            uint32_t off = r * 128 + (sp * 16 + 2 * t) * 2;
            uint32_t sw = off ^ ((r & 7) << 4);
            *(uint32_t*)(smem + c * C1_STG + sw) = bf_pack(v0, v1);
        }
    }
    CP_COMMIT();
    CP_WAIT(0);
    __syncthreads();

    #pragma unroll
    for (int c = 0; c < 2; c++) {
        const uint32_t s0 = sb + c * C1_STG;
        #pragma unroll
        for (int ks = 0; ks < 4; ks++) {
            uint32_t B[8][2];
            const int brow = ks * 16 + lane15;
            #pragma unroll
            for (int q = 0; q < 4; q++) {
                uint32_t off = brow * 512 + wn * 128 + q * 32 + lane16 * 16;
                uint32_t sw = off ^ ((brow & 7) << 4);
                ldsm_x4_t(B[2*q][0], B[2*q][1], B[2*q+1][0], B[2*q+1][1], s0 + 16384 + sw);
            }
            #pragma unroll
            for (int ma = 0; ma < 2; ma++) {
                const int arow = wm * 32 + ma * 16 + lane15;
                uint32_t offA = arow * 128 + ks * 32 + lane16 * 16;
                uint32_t swA = offA ^ ((arow & 7) << 4);
                uint32_t a[4];
                ldsm_x4(a[0], a[1], a[2], a[3], s0 + swA);
                #pragma unroll
                for (int na = 0; na < 8; na++) mma16816(acc[ma][na], a, B[na]);
            }
        }
    }

    #pragma unroll
    for (int ma = 0; ma < 2; ma++)
        #pragma unroll
        for (int h = 0; h < 2; h++) {
            int p = tile * 128 + wm * 32 + ma * 16 + h * 8 + gid;
            if (p >= 50176) continue;
            __nv_bfloat16* op = ob16 + (size_t)p * 256;
            #pragma unroll
            for (int na = 0; na < 8; na++) {
                int oc = wn * 64 + na * 8 + tig * 2;
                float v0 = fmaxf(acc[ma][na][h * 2 + 0] + bias[oc],     0.f);
                float v1 = fmaxf(acc[ma][na][h * 2 + 1] + bias[oc + 1], 0.f);
                *(uint32_t*)(op + oc) = bf_pack(v0, v1);
            }
        }
}

// ---------------- conv2/pc: 256 thr, 128x128 tile, 2 CTAs/SM, 3-stage, bf16 partials ----------------
#define STG 32768
#define SMEM_CONV_TOTAL (3 * STG)

template<int IH, int IW, int OH, int OW, int KW, int STRIDE, int NCHUNK, int KSPLIT, int NPOS>
__global__ __launch_bounds__(256, 2)
void conv_mma_kernel(const __nv_bfloat16* __restrict__ inb,
                     const __nv_bfloat16* __restrict__ wb,
                     __nv_bfloat16* __restrict__ partb) {
    extern __shared__ char smem[];
    const uint32_t sb = smem_to_u32(smem);
    const int tid = threadIdx.x;
    const int wid = tid >> 5, lid = tid & 31;
    const int tile = blockIdx.x, ntile = blockIdx.y;

    const int r = tid >> 1, sp = tid & 1;
    const int p_mine = tile * 128 + r;
    const bool pvalid = p_mine < NPOS;
    int pb = 0, pr = 0, pcx = 0;
    if (pvalid) {
        pb = p_mine / (OH * OW);
        int rem = p_mine - pb * (OH * OW);
        pr = rem / OW;
        pcx = rem - pr * OW;
    }
    const int asz = pvalid ? 16 : 0;

    const int wm = wid >> 1, wn = wid & 1;
    const int lane15 = lid & 15, lane16 = lid >> 4;
    const int gid = lid >> 2, tig = lid & 3;

    float acc[2][8][4];
    #pragma unroll
    for (int ma = 0; ma < 2; ma++)
        #pragma unroll
        for (int na = 0; na < 8; na++)
            #pragma unroll
            for (int q = 0; q < 4; q++) acc[ma][na][q] = 0.f;

    const int NC = NCHUNK / KSPLIT;
    const int coff = blockIdx.z * NC;

    auto fill = [&](int stage, int chunk) {
        uint32_t s0 = sb + stage * STG;
        const char* bsrc = (const char*)(wb + (size_t)(chunk * 2 + ntile) * 8192);
        #pragma unroll
        for (int i = 0; i < 4; i++) {
            uint32_t u = (tid + i * 256) * 16;
            CP_ASYNC16(s0 + 16384 + u, bsrc + u, 16);
        }
        const int kyx = chunk >> 2;
        const int ic0 = (chunk & 3) * 64;
        const int ky = kyx / KW, kx = kyx % KW;
        size_t srcbase = 0;
        if (pvalid) {
            int iy = pr * STRIDE + ky, ix = pcx * STRIDE + kx;
            srcbase = (((size_t)pb * IH + iy) * IW + ix) * 256 + ic0;
        }
        #pragma unroll
        for (int q = 0; q < 4; q++) {
            int seg = sp * 4 + q;
            uint32_t off = r * 128 + seg * 16;
            uint32_t sw = off ^ ((r & 7) << 4);
            CP_ASYNC16(s0 + sw, (const char*)(inb + srcbase + seg * 8), asz);
        }
    };

    fill(0, coff);              CP_COMMIT();
    if (NC > 1) { fill(1, coff + 1); CP_COMMIT(); }

    int st = 0;
    for (int i = 0; i < NC; ++i) {
        if (i + 1 < NC) { CP_WAIT(1); } else { CP_WAIT(0); }
        __syncthreads();

        const uint32_t s0 = sb + st * STG;
        #pragma unroll
        for (int ks = 0; ks < 4; ks++) {
            uint32_t B[8][2];
            const int brow = ks * 16 + lane15;
            #pragma unroll
            for (int q = 0; q < 4; q++) {
                uint32_t off = brow * 256 + wn * 128 + q * 32 + lane16 * 16;
                uint32_t sw = off ^ ((brow & 7) << 4);
                ldsm_x4_t(B[2*q][0], B[2*q][1], B[2*q+1][0], B[2*q+1][1], s0 + 16384 + sw);
            }
            #pragma unroll
            for (int ma = 0; ma < 2; ma++) {
                const int arow = wm * 32 + ma * 16 + lane15;
                uint32_t offA = arow * 128 + ks * 32 + lane16 * 16;
                uint32_t swA = offA ^ ((arow & 7) << 4);
                uint32_t a[4];
                ldsm_x4(a[0], a[1], a[2], a[3], s0 + swA);
                #pragma unroll
                for (int na = 0; na < 8; na++) mma16816(acc[ma][na], a, B[na]);
            }
            if (ks == 0 && i + 2 < NC) { fill((st + 2) % 3, coff + i + 2); CP_COMMIT(); }
        }
        st = (st + 1) % 3;
    }

    __nv_bfloat16* op0 = partb + (size_t)blockIdx.z * NPOS * 256;
    #pragma unroll
    for (int ma = 0; ma < 2; ma++)
        #pragma unroll
        for (int h = 0; h < 2; h++) {
            int p = tile * 128 + wm * 32 + ma * 16 + h * 8 + gid;
            if (p >= NPOS) continue;
            __nv_bfloat16* op = op0 + (size_t)p * 256 + ntile * 128 + wn * 64 + tig * 2;
            #pragma unroll
            for (int na = 0; na < 8; na++)
                *(uint32_t*)(op + na * 8) = bf_pack(acc[ma][na][h * 2], acc[ma][na][h * 2 + 1]);
        }
}

// ---------------- reduce conv2 (2-way bf16) -> bias+relu -> bf16 NHWC ----------------
__global__ void reduce2_kernel(const __nv_bfloat16* __restrict__ partb,
                               const float* __restrict__ bias,
                               __nv_bfloat16* __restrict__ ob16) {
    size_t gid = (size_t)blockIdx.x * 256 + threadIdx.x;
    if (gid >= (size_t)43264 * 128) return;
    int p = (int)(gid >> 7);
    int oc = ((int)gid & 127) * 2;
    const size_t half = (size_t)43264 * 256;
    uint32_t ua = *(const uint32_t*)(partb + (size_t)p * 256 + oc);
    uint32_t ub = *(const uint32_t*)(partb + half + (size_t)p * 256 + oc);
    float v0 = fmaxf(bf_lo(ua) + bf_lo(ub) + bias[oc],     0.f);
    float v1 = fmaxf(bf_hi(ua) + bf_hi(ub) + bias[oc + 1], 0.f);
    *(uint32_t*)(ob16 + (size_t)p * 256 + oc) = bf_pack(v0, v1);
}

// ---------------- reduce pc partials (12-way bf16) -> bias -> fp32 NCHW ----------------
__global__ void reducep_kernel(const __nv_bfloat16* __restrict__ partb,
                               const float* __restrict__ bias,
                               float* __restrict__ out) {
    int gid = blockIdx.x * 256 + threadIdx.x;
    if (gid >= 7744 * 64) return;
    int p = gid >> 6, oc = (gid & 63) * 4;
    const size_t seg = (size_t)7744 * 256;
    float v[4];
    const float4 bv = *(const float4*)(bias + oc);
    v[0] = bv.x; v[1] = bv.y; v[2] = bv.z; v[3] = bv.w;
    #pragma unroll
    for (int k = 0; k < 12; k++) {
        const uint32_t* q = (const uint32_t*)(partb + k * seg + (size_t)p * 256 + oc);
        uint32_t u0 = q[0], u1 = q[1];
        v[0] += bf_lo(u0); v[1] += bf_hi(u0);
        v[2] += bf_lo(u1); v[3] += bf_hi(u1);
    }
    int b = p / 484;
    int rem = p - b * 484;
    int rr = rem / 22, cx = rem - rr * 22;
    size_t base = (((size_t)b * 256 + oc) * 22 + rr) * 22 + cx;
    out[base] = v[0]; out[base + 484] = v[1];
    out[base + 2 * 484] = v[2]; out[base + 3 * 484] = v[3];
}

// ---------------- squash ----------------
__global__ void squash_u_kernel() {
    int cap = blockIdx.x * 256 + threadIdx.x;
    if (cap >= BATCH * NI) return;
    const float4* pp = (const float4*)(g_p + (size_t)cap * 8);
    float4 a = pp[0], c = pp[1];
    float s2 = a.x*a.x + a.y*a.y + a.z*a.z + a.w*a.w + c.x*c.x + c.y*c.y + c.z*c.z + c.w*c.w;
    float f = s2 / (1.f + s2) * rsqrtf(s2 + EPSQ);
    a.x *= f; a.y *= f; a.z *= f; a.w *= f;
    c.x *= f; c.y *= f; c.z *= f; c.w *= f;
    float4* uo = (float4*)(g_u + (size_t)cap * 8);
    uo[0] = a; uo[1] = c;
}

// ---------------- u_hat (bf16) + fused round-1 s ----------------
__global__ __launch_bounds__(256)
void uhat_kernel(const float* __restrict__ W) {
    __shared__ float ssh[2560];
    int tid = threadIdx.x;
    for (int t = tid; t < 2560; t += 256) ssh[t] = 0.f;
    __syncthreads();

    int gid = blockIdx.x * 256 + tid;
    int d = gid & 15;
    int j = (gid >> 4) % 10;
    int i = gid / 160;
    if (i < NI) {
        const float4* Wp = (const float4*)(W + (((size_t)j * NI + i) * 16 + d) * 8);
        float4 w0 = Wp[0], w1 = Wp[1];
        for (int b = 0; b < BATCH; b++) {
            const float4* up = (const float4*)(g_u + ((size_t)b * NI + i) * 8);
            float4 u0 = up[0], u1 = up[1];
            float acc = w0.x*u0.x + w0.y*u0.y + w0.z*u0.z + w0.w*u0.w
                      + w1.x*u1.x + w1.y*u1.y + w1.z*u1.z + w1.w*u1.w;
            g_uhatb[(((size_t)b * NI + i) * 10 + j) * 16 + d] = __float2bfloat16(acc);
            atomicAdd(&ssh[b * 160 + j * 16 + d], acc);
        }
    }
    __syncthreads();
    for (int t = tid; t < 2560; t += 256)
        if (ssh[t] != 0.f) atomicAdd(&g_s[t], 0.1f * ssh[t]);
}

// ---------------- routing (rounds 2,3) ----------------
__global__ __launch_bounds__(256)
void routing_s_kernel() {
    __shared__ float Vsh[160];
    __shared__ float ssh[160];
    int tid = threadIdx.x;
    int b = blockIdx.y;
    if (tid < 160) { Vsh[tid] = g_V[b * 160 + tid]; ssh[tid] = 0.f; }
    __syncthreads();
    int d = tid & 15, il = tid >> 4;
    float accj[10];
    #pragma unroll
    for (int j = 0; j < 10; j++) accj[j] = 0.f;
    const int per = NI / 32;
    int i0 = blockIdx.x * per;
    for (int i = i0 + il; i < i0 + per; i += 16) {
        const __nv_bfloat16* uh = g_uhatb + (((size_t)b * NI + i) * 10) * 16 + d;
        float uv[10], e[10];
        float m = -1e30f;
        #pragma unroll
        for (int j = 0; j < 10; j++) {
            uv[j] = __bfloat162float(uh[j * 16]);
            float l = uv[j] * Vsh[j * 16 + d];
            e[j] = l;
            m = fmaxf(m, l);
        }
        float se = 0.f;
        #pragma unroll
        for (int j = 0; j < 10; j++) { e[j] = __expf(e[j] - m); se += e[j]; }
        float inv = 1.f / se;
        #pragma unroll
        for (int j = 0; j < 10; j++) accj[j] += e[j] * inv * uv[j];
    }
    #pragma unroll
    for (int j = 0; j < 10; j++) atomicAdd(&ssh[j * 16 + d], accj[j]);
    __syncthreads();
    if (tid < 160) atomicAdd(&g_s[b * 160 + tid], ssh[tid]);
}

__global__ void v_update_kernel(int last, float* __restrict__ dout) {
    __shared__ float s2sh[10];
    __shared__ float nrm[10];
    __shared__ int amax;
    int b = blockIdx.x, tid = threadIdx.x;
    int j = tid >> 4, d = tid & 15;
    if (tid < 10) s2sh[tid] = 0.f;
    __syncthreads();
    float sv = g_s[b * 160 + tid];
    atomicAdd(&s2sh[j], sv * sv);
    __syncthreads();
    float s2 = s2sh[j];
    float v = s2 / (1.f + s2) * sv * rsqrtf(s2 + EPSQ);
    if (!last) {
        g_V[b * 160 + tid] += v;
    } else {
        if (d == 0) nrm[j] = s2 / (1.f + s2) * sqrtf(s2) * rsqrtf(s2 + EPSQ);
        __syncthreads();
        if (tid == 0) {
            int bm = 0; float mx = nrm[0];
            for (int jj = 1; jj < 10; jj++)
                if (nrm[jj] > mx) { mx = nrm[jj]; bm = jj; }
            amax = bm;
        }
        if (d == 0) dout[b * 10 + j] = nrm[j];
        __syncthreads();
        g_masked[b * 160 + tid] = (j == amax) ? v : 0.f;
    }
}

// ---------------- decoder FC: all 16 batches per block (W read once) ----------------
__global__ void fc_multi_kernel(const float* __restrict__ in, const float* __restrict__ W,
                                const float* __restrict__ bias, float* __restrict__ out,
                                int IN, int OUT, int act) {
    extern __shared__ float s_in[];   // [16 * IN]
    int tid = threadIdx.x;
    for (int t = tid; t < 16 * IN; t += blockDim.x) s_in[t] = in[t];
    __syncthreads();
    int o = blockIdx.x * blockDim.x + tid;
    if (o >= OUT) return;
    float bv = bias[o];
    float acc[16];
    #pragma unroll
    for (int b = 0; b < 16; b++) acc[b] = bv;
    for (int k = 0; k < IN; k++) {
        float w = W[(size_t)k * OUT + o];
        #pragma unroll
        for (int b = 0; b < 16; b++) acc[b] += s_in[b * IN + k] * w;
    }
    #pragma unroll
    for (int b = 0; b < 16; b++) {
        float v = acc[b];
        if (act == 1) v = fmaxf(v, 0.f);
        else          v = 1.f / (1.f + __expf(-v));
        out[(size_t)b * OUT + o] = v;
    }
}

// ---------------- launch ----------------
extern "C" void kernel_launch(void* const* d_in, const int* in_sizes, int n_in,
                              void* d_out, int out_size) {
    const float* x   = (const float*)d_in[0];
    const float* c1w = (const float*)d_in[1];
    const float* c1b = (const float*)d_in[2];
    const float* c2w = (const float*)d_in[3];
    const float* c2b = (const float*)d_in[4];
    const float* pcw = (const float*)d_in[5];
    const float* pcb = (const float*)d_in[6];
    const float* Wc  = (const float*)d_in[7];
    const float* w1  = (const float*)d_in[8];
    const float* b1  = (const float*)d_in[9];
    const float* w2  = (const float*)d_in[10];
    const float* b2  = (const float*)d_in[11];
    const float* w3  = (const float*)d_in[12];
    const float* b3  = (const float*)d_in[13];
    float* dout = (float*)d_out;

    __nv_bfloat16 *p_c1b, *p_c2b, *p_partb, *p_w1b, *p_w2b, *p_wpb;
    float *p_p, *p_s, *p_V, *p_masked, *p_d1, *p_d2;
    cudaGetSymbolAddress((void**)&p_c1b, g_c1b);
    cudaGetSymbolAddress((void**)&p_c2b, g_c2b);
    cudaGetSymbolAddress((void**)&p_partb, g_partb);
    cudaGetSymbolAddress((void**)&p_p,  g_p);
    cudaGetSymbolAddress((void**)&p_w1b, g_w1b);
    cudaGetSymbolAddress((void**)&p_w2b, g_w2b);
    cudaGetSymbolAddress((void**)&p_wpb, g_wpb);
    cudaGetSymbolAddress((void**)&p_s,  g_s);
    cudaGetSymbolAddress((void**)&p_V,  g_V);
    cudaGetSymbolAddress((void**)&p_masked, g_masked);
    cudaGetSymbolAddress((void**)&p_d1, g_d1);
    cudaGetSymbolAddress((void**)&p_d2, g_d2);

    auto conv2 = conv_mma_kernel<56, 56, 52, 52, 5, 1, 100, 2, 43264>;
    auto convp = conv_mma_kernel<52, 52, 22, 22, 9, 2, 324, 12, 7744>;
    cudaFuncSetAttribute(conv2, cudaFuncAttributeMaxDynamicSharedMemorySize, SMEM_CONV_TOTAL);
    cudaFuncSetAttribute(convp, cudaFuncAttributeMaxDynamicSharedMemorySize, SMEM_CONV_TOTAL);
    cudaFuncSetAttribute(conv1_mma_kernel, cudaFuncAttributeMaxDynamicSharedMemorySize, C1_SMEM);
    cudaFuncSetAttribute(fc_multi_kernel, cudaFuncAttributeMaxDynamicSharedMemorySize, 66560);

    transform_w1_kernel<<<(2 * 64 * 128 + 255) / 256, 256>>>(c1w, p_w1b);
    transform_w_kernel<<<(100 * 8192 + 255) / 256, 256>>>(c2w, p_w2b, 5, 5, 100);
    transform_w_kernel<<<(324 * 8192 + 255) / 256, 256>>>(pcw, p_wpb, 9, 9, 324);

    conv1_mma_kernel<<<392, 512, C1_SMEM>>>(x, p_w1b, c1b, p_c1b);

    conv2<<<dim3(338, 2, 2), 256, SMEM_CONV_TOTAL>>>(p_c1b, p_w2b, p_partb);
    reduce2_kernel<<<(int)(((size_t)43264 * 128 + 255) / 256), 256>>>(p_partb, c2b, p_c2b);

    convp<<<dim3(61, 2, 12), 256, SMEM_CONV_TOTAL>>>(p_c2b, p_wpb, p_partb);
    reducep_kernel<<<(7744 * 64 + 255) / 256, 256>>>(p_partb, pcb, p_p);

    squash_u_kernel<<<(BATCH * NI + 255) / 256, 256>>>();

    cudaMemsetAsync(p_V, 0, BATCH * 160 * sizeof(float));
    cudaMemsetAsync(p_s, 0, BATCH * 160 * sizeof(float));
    uhat_kernel<<<((size_t)NI * 160 + 255) / 256, 256>>>(Wc);
    v_update_kernel<<<16, 160>>>(0, dout);

    for (int r = 1; r < 3; r++) {
        cudaMemsetAsync(p_s, 0, BATCH * 160 * sizeof(float));
        routing_s_kernel<<<dim3(32, 16), 256>>>();
        v_update_kernel<<<16, 160>>>(r == 2 ? 1 : 0, dout);
    }

    fc_multi_kernel<<<2, 256, 16 * 160 * 4>>>(p_masked, w1, b1, p_d1, 160, 512, 1);
    fc_multi_kernel<<<4, 256, 16 * 512 * 4>>>(p_d1, w2, b2, p_d2, 512, 1024, 1);
    fc_multi_kernel<<<16, 256, 16 * 1024 * 4>>>(p_d2, w3, b3, dout + 160, 1024, 4096, 2);
}

// round 16
// speedup vs baseline: 1.3329x; 1.3329x over previous
#include <cuda_runtime.h>
#include <cuda_bf16.h>
#include <cstdint>

#define EPSQ 1e-8f
static const int BATCH = 16;
static const int NI = 15488;

// ---------------- scratch ----------------
__device__ __nv_bfloat16 g_c1b[(size_t)50176 * 256];
__device__ __nv_bfloat16 g_c2b[(size_t)43264 * 256];
__device__ float g_part[(size_t)12 * 7744 * 256];
__device__ float g_p [(size_t)16 * 256 * 22 * 22];
__device__ float g_u [(size_t)16 * 15488 * 8];
__device__ __nv_bfloat16 g_uhatb[(size_t)16 * 15488 * 10 * 16];
__device__ __nv_bfloat16 g_w1b[(size_t)2 * 16384];
__device__ __nv_bfloat16 g_w2b[(size_t)200 * 8192];
__device__ __nv_bfloat16 g_wpb[(size_t)648 * 8192];
__device__ float g_s[16 * 160];
__device__ float g_V[16 * 160];
__device__ float g_masked[16 * 160];
__device__ float g_d1[16 * 512];
__device__ float g_d2[16 * 1024];

// ---------------- helpers ----------------
__device__ __forceinline__ uint32_t smem_to_u32(const void* p) {
    uint32_t a;
    asm("{ .reg .u64 t; cvta.to.shared.u64 t, %1; cvt.u32.u64 %0, t; }" : "=r"(a) : "l"(p));
    return a;
}
__device__ __forceinline__ void ldsm_x4(uint32_t& r0, uint32_t& r1, uint32_t& r2, uint32_t& r3, uint32_t addr) {
    asm volatile("ldmatrix.sync.aligned.m8n8.x4.shared.b16 {%0,%1,%2,%3}, [%4];"
                 : "=r"(r0), "=r"(r1), "=r"(r2), "=r"(r3) : "r"(addr));
}
__device__ __forceinline__ void ldsm_x4_t(uint32_t& r0, uint32_t& r1, uint32_t& r2, uint32_t& r3, uint32_t addr) {
    asm volatile("ldmatrix.sync.aligned.m8n8.x4.trans.shared.b16 {%0,%1,%2,%3}, [%4];"
                 : "=r"(r0), "=r"(r1), "=r"(r2), "=r"(r3) : "r"(addr));
}
__device__ __forceinline__ void mma16816(float* c, const uint32_t* a, const uint32_t* b) {
    asm volatile("mma.sync.aligned.m16n8k16.row.col.f32.bf16.bf16.f32 "
                 "{%0,%1,%2,%3}, {%4,%5,%6,%7}, {%8,%9}, {%0,%1,%2,%3};"
                 : "+f"(c[0]), "+f"(c[1]), "+f"(c[2]), "+f"(c[3])
                 : "r"(a[0]), "r"(a[1]), "r"(a[2]), "r"(a[3]), "r"(b[0]), "r"(b[1]));
}
#define CP_ASYNC16(dst, src, sz) \
    asm volatile("cp.async.cg.shared.global [%0], [%1], 16, %2;" :: "r"(dst), "l"(src), "r"(sz))
#define CP_COMMIT() asm volatile("cp.async.commit_group;" ::: "memory")
#define CP_WAIT(n)  asm volatile("cp.async.wait_group %0;" :: "n"(n) : "memory")

__device__ __forceinline__ uint32_t bf_pack(float a, float b) {
    return ((uint32_t)__bfloat16_as_ushort(__float2bfloat16(b)) << 16)
         | __bfloat16_as_ushort(__float2bfloat16(a));
}

// ---------------- weight transforms ----------------
__global__ void transform_w_kernel(const float* __restrict__ w,
                                   __nv_bfloat16* __restrict__ wb,
                                   int KH, int KW, int NCHUNK) {
    int idx = blockIdx.x * 256 + threadIdx.x;
    int total = NCHUNK * 2 * 64 * 64;
    if (idx >= total) return;
    int np = idx & 63;
    int k  = (idx >> 6) & 63;
    int ntile = (idx >> 12) & 1;
    int chunk = idx >> 13;
    int kyx = chunk >> 2;
    int ic = (chunk & 3) * 64 + k;
    int ky = kyx / KW, kx = kyx % KW;
    int oc = ntile * 128 + np * 2;
    size_t KHW = (size_t)KH * KW;
    size_t wi = (((size_t)oc * 256 + ic) * KH + ky) * KW + kx;
    uint32_t pk = bf_pack(w[wi], w[wi + 256 * KHW]);
    int off = k * 256 + np * 4;
    int sw = off ^ ((k & 7) << 4);
    *(uint32_t*)((char*)wb + (size_t)(chunk * 2 + ntile) * 16384 + sw) = pk;
}

__global__ void transform_w1_kernel(const float* __restrict__ w,
                                    __nv_bfloat16* __restrict__ wb) {
    int idx = blockIdx.x * 256 + threadIdx.x;
    if (idx >= 2 * 64 * 128) return;
    int np = idx & 127;
    int k  = (idx >> 7) & 63;
    int chunk = idx >> 13;
    int kk = chunk * 64 + k;
    int oc = np * 2;
    float f0 = (kk < 81) ? w[(size_t)oc * 81 + kk] : 0.f;
    float f1 = (kk < 81) ? w[(size_t)(oc + 1) * 81 + kk] : 0.f;
    int off = k * 512 + np * 4;
    int sw = off ^ ((k & 7) << 4);
    *(uint32_t*)((char*)wb + (size_t)chunk * 32768 + sw) = bf_pack(f0, f1);
}

// ---------------- conv1 via HMMA ----------------
#define C1_STG 49152
#define C1_SMEM (2 * C1_STG)

__global__ __launch_bounds__(512, 1)
void conv1_mma_kernel(const float* __restrict__ x,
                      const __nv_bfloat16* __restrict__ wb,
                      const float* __restrict__ bias,
                      __nv_bfloat16* __restrict__ ob16) {
    extern __shared__ char smem[];
    const uint32_t sb = smem_to_u32(smem);
    const int tid = threadIdx.x;
    const int wid = tid >> 5, lid = tid & 31;
    const int tile = blockIdx.x;

    const int r = tid >> 2, sp = tid & 3;
    const int p_mine = tile * 128 + r;
    const bool pvalid = p_mine < 50176;
    int pb = 0, pr = 0, pcx = 0;
    if (pvalid) {
        pb = p_mine / 3136;
        int rem = p_mine - pb * 3136;
        pr = rem / 56;
        pcx = rem - pr * 56;
    }

    const int wm = wid >> 2, wn = wid & 3;
    const int lane15 = lid & 15, lane16 = lid >> 4;
    const int gid = lid >> 2, tig = lid & 3;

    float acc[2][8][4];
    #pragma unroll
    for (int ma = 0; ma < 2; ma++)
        #pragma unroll
        for (int na = 0; na < 8; na++)
            #pragma unroll
            for (int q = 0; q < 4; q++) acc[ma][na][q] = 0.f;

    #pragma unroll
    for (int c = 0; c < 2; c++) {
        uint32_t s0 = sb + c * C1_STG;
        const char* bsrc = (const char*)(wb + (size_t)c * 16384);
        #pragma unroll
        for (int i = 0; i < 4; i++) {
            uint32_t u = (tid + i * 512) * 16;
            CP_ASYNC16(s0 + 16384 + u, bsrc + u, 16);
        }
        const float* xb = x + (size_t)pb * 4096;
        #pragma unroll
        for (int t = 0; t < 8; t++) {
            int k0 = c * 64 + sp * 16 + 2 * t;
            float v0 = 0.f, v1 = 0.f;
            if (pvalid && k0 < 81) {
                int ky = k0 / 9, kx = k0 - 9 * ky;
                v0 = xb[(pr + ky) * 64 + pcx + kx];
            }
            if (pvalid && k0 + 1 < 81) {
                int ky = (k0 + 1) / 9, kx = (k0 + 1) - 9 * ky;
                v1 = xb[(pr + ky) * 64 + pcx + kx];
            }
            uint32_t off = r * 128 + (sp * 16 + 2 * t) * 2;
            uint32_t sw = off ^ ((r & 7) << 4);
            *(uint32_t*)(smem + c * C1_STG + sw) = bf_pack(v0, v1);
        }
    }
    CP_COMMIT();
    CP_WAIT(0);
    __syncthreads();

    #pragma unroll
    for (int c = 0; c < 2; c++) {
        const uint32_t s0 = sb + c * C1_STG;
        #pragma unroll
        for (int ks = 0; ks < 4; ks++) {
            uint32_t B[8][2];
            const int brow = ks * 16 + lane15;
            #pragma unroll
            for (int q = 0; q < 4; q++) {
                uint32_t off = brow * 512 + wn * 128 + q * 32 + lane16 * 16;
                uint32_t sw = off ^ ((brow & 7) << 4);
                ldsm_x4_t(B[2*q][0], B[2*q][1], B[2*q+1][0], B[2*q+1][1], s0 + 16384 + sw);
            }
            #pragma unroll
            for (int ma = 0; ma < 2; ma++) {
                const int arow = wm * 32 + ma * 16 + lane15;
                uint32_t offA = arow * 128 + ks * 32 + lane16 * 16;
                uint32_t swA = offA ^ ((arow & 7) << 4);
                uint32_t a[4];
                ldsm_x4(a[0], a[1], a[2], a[3], s0 + swA);
                #pragma unroll
                for (int na = 0; na < 8; na++) mma16816(acc[ma][na], a, B[na]);
            }
        }
    }

    #pragma unroll
    for (int ma = 0; ma < 2; ma++)
        #pragma unroll
        for (int h = 0; h < 2; h++) {
            int p = tile * 128 + wm * 32 + ma * 16 + h * 8 + gid;
            if (p >= 50176) continue;
            __nv_bfloat16* op = ob16 + (size_t)p * 256;
            #pragma unroll
            for (int na = 0; na < 8; na++) {
                int oc = wn * 64 + na * 8 + tig * 2;
                float v0 = fmaxf(acc[ma][na][h * 2 + 0] + bias[oc],     0.f);
                float v1 = fmaxf(acc[ma][na][h * 2 + 1] + bias[oc + 1], 0.f);
                *(uint32_t*)(op + oc) = bf_pack(v0, v1);
            }
        }
}

// ---------------- conv2/pc: 256 thr, 128x128 tile, 2 CTAs/SM, 3-stage, fp32 partials ----------------
#define STG 32768
#define SMEM_CONV_TOTAL (3 * STG)

template<int IH, int IW, int OH, int OW, int KW, int STRIDE, int NCHUNK, int KSPLIT, int NPOS>
__global__ __launch_bounds__(256, 2)
void conv_mma_kernel(const __nv_bfloat16* __restrict__ inb,
                     const __nv_bfloat16* __restrict__ wb,
                     float* __restrict__ part) {
    extern __shared__ char smem[];
    const uint32_t sb = smem_to_u32(smem);
    const int tid = threadIdx.x;
    const int wid = tid >> 5, lid = tid & 31;
    const int tile = blockIdx.x, ntile = blockIdx.y;

    const int r = tid >> 1, sp = tid & 1;
    const int p_mine = tile * 128 + r;
    const bool pvalid = p_mine < NPOS;
    int pb = 0, pr = 0, pcx = 0;
    if (pvalid) {
        pb = p_mine / (OH * OW);
        int rem = p_mine - pb * (OH * OW);
        pr = rem / OW;
        pcx = rem - pr * OW;
    }
    const int asz = pvalid ? 16 : 0;

    const int wm = wid >> 1, wn = wid & 1;
    const int lane15 = lid & 15, lane16 = lid >> 4;
    const int gid = lid >> 2, tig = lid & 3;

    float acc[2][8][4];
    #pragma unroll
    for (int ma = 0; ma < 2; ma++)
        #pragma unroll
        for (int na = 0; na < 8; na++)
            #pragma unroll
            for (int q = 0; q < 4; q++) acc[ma][na][q] = 0.f;

    const int NC = NCHUNK / KSPLIT;
    const int coff = blockIdx.z * NC;

    auto fill = [&](int stage, int chunk) {
        uint32_t s0 = sb + stage * STG;
        const char* bsrc = (const char*)(wb + (size_t)(chunk * 2 + ntile) * 8192);
        #pragma unroll
        for (int i = 0; i < 4; i++) {
            uint32_t u = (tid + i * 256) * 16;
            CP_ASYNC16(s0 + 16384 + u, bsrc + u, 16);
        }
        const int kyx = chunk >> 2;
        const int ic0 = (chunk & 3) * 64;
        const int ky = kyx / KW, kx = kyx % KW;
        size_t srcbase = 0;
        if (pvalid) {
            int iy = pr * STRIDE + ky, ix = pcx * STRIDE + kx;
            srcbase = (((size_t)pb * IH + iy) * IW + ix) * 256 + ic0;
        }
        #pragma unroll
        for (int q = 0; q < 4; q++) {
            int seg = sp * 4 + q;
            uint32_t off = r * 128 + seg * 16;
            uint32_t sw = off ^ ((r & 7) << 4);
            CP_ASYNC16(s0 + sw, (const char*)(inb + srcbase + seg * 8), asz);
        }
    };

    fill(0, coff);              CP_COMMIT();
    if (NC > 1) { fill(1, coff + 1); CP_COMMIT(); }

    int st = 0;
    for (int i = 0; i < NC; ++i) {
        if (i + 1 < NC) { CP_WAIT(1); } else { CP_WAIT(0); }
        __syncthreads();

        const uint32_t s0 = sb + st * STG;
        #pragma unroll
        for (int ks = 0; ks < 4; ks++) {
            uint32_t B[8][2];
            const int brow = ks * 16 + lane15;
            #pragma unroll
            for (int q = 0; q < 4; q++) {
                uint32_t off = brow * 256 + wn * 128 + q * 32 + lane16 * 16;
                uint32_t sw = off ^ ((brow & 7) << 4);
                ldsm_x4_t(B[2*q][0], B[2*q][1], B[2*q+1][0], B[2*q+1][1], s0 + 16384 + sw);
            }
            #pragma unroll
            for (int ma = 0; ma < 2; ma++) {
                const int arow = wm * 32 + ma * 16 + lane15;
                uint32_t offA = arow * 128 + ks * 32 + lane16 * 16;
                uint32_t swA = offA ^ ((arow & 7) << 4);
                uint32_t a[4];
                ldsm_x4(a[0], a[1], a[2], a[3], s0 + swA);
                #pragma unroll
                for (int na = 0; na < 8; na++) mma16816(acc[ma][na], a, B[na]);
            }
            if (ks == 0 && i + 2 < NC) { fill((st + 2) % 3, coff + i + 2); CP_COMMIT(); }
        }
        st = (st + 1) % 3;
    }

    float* op0 = part + (size_t)blockIdx.z * NPOS * 256;
    #pragma unroll
    for (int ma = 0; ma < 2; ma++)
        #pragma unroll
        for (int h = 0; h < 2; h++) {
            int p = tile * 128 + wm * 32 + ma * 16 + h * 8 + gid;
            if (p >= NPOS) continue;
            float* op = op0 + (size_t)p * 256 + ntile * 128 + wn * 64 + tig * 2;
            #pragma unroll
            for (int na = 0; na < 8; na++)
                *(float2*)(op + na * 8) = make_float2(acc[ma][na][h * 2], acc[ma][na][h * 2 + 1]);
        }
}

// ---------------- reduce conv2 (2-way) -> bias+relu -> bf16 NHWC ----------------
__global__ void reduce2_kernel(const float* __restrict__ part, const float* __restrict__ bias,
                               __nv_bfloat16* __restrict__ ob16) {
    size_t gid = (size_t)blockIdx.x * 256 + threadIdx.x;
    if (gid >= (size_t)43264 * 128) return;
    int p = (int)(gid >> 7);
    int oc = ((int)gid & 127) * 2;
    const float* p0 = part + (size_t)p * 256 + oc;
    const size_t half = (size_t)43264 * 256;
    float v0 = fmaxf(p0[0] + p0[half]     + bias[oc],     0.f);
    float v1 = fmaxf(p0[1] + p0[half + 1] + bias[oc + 1], 0.f);
    *(uint32_t*)(ob16 + (size_t)p * 256 + oc) = bf_pack(v0, v1);
}

// ---------------- reduce pc partials (12-way) -> bias -> fp32 NCHW ----------------
__global__ void reducep_kernel(const float* __restrict__ part, const float* __restrict__ bias,
                               float* __restrict__ out) {
    int gid = blockIdx.x * 256 + threadIdx.x;
    if (gid >= 7744 * 64) return;
    int p = gid >> 6, oc = (gid & 63) * 4;
    const size_t seg = (size_t)7744 * 256;
    const float* p0 = part + (size_t)p * 256 + oc;
    float4 v = *(const float4*)p0;
    #pragma unroll
    for (int k = 1; k < 12; k++) {
        float4 t = *(const float4*)(p0 + k * seg);
        v.x += t.x; v.y += t.y; v.z += t.z; v.w += t.w;
    }
    const float4 bv = *(const float4*)(bias + oc);
    v.x += bv.x; v.y += bv.y; v.z += bv.z; v.w += bv.w;
    int b = p / 484;
    int rem = p - b * 484;
    int rr = rem / 22, cx = rem - rr * 22;
    size_t base = (((size_t)b * 256 + oc) * 22 + rr) * 22 + cx;
    out[base] = v.x; out[base + 484] = v.y;
    out[base + 2 * 484] = v.z; out[base + 3 * 484] = v.w;
}

// ---------------- squash ----------------
__global__ void squash_u_kernel() {
    int cap = blockIdx.x * 256 + threadIdx.x;
    if (cap >= BATCH * NI) return;
    const float4* pp = (const float4*)(g_p + (size_t)cap * 8);
    float4 a = pp[0], c = pp[1];
    float s2 = a.x*a.x + a.y*a.y + a.z*a.z + a.w*a.w + c.x*c.x + c.y*c.y + c.z*c.z + c.w*c.w;
    float f = s2 / (1.f + s2) * rsqrtf(s2 + EPSQ);
    a.x *= f; a.y *= f; a.z *= f; a.w *= f;
    c.x *= f; c.y *= f; c.z *= f; c.w *= f;
    float4* uo = (float4*)(g_u + (size_t)cap * 8);
    uo[0] = a; uo[1] = c;
}

// ---------------- u_hat (bf16) + fused round-1 s ----------------
__global__ __launch_bounds__(256)
void uhat_kernel(const float* __restrict__ W) {
    __shared__ float ssh[2560];
    int tid = threadIdx.x;
    for (int t = tid; t < 2560; t += 256) ssh[t] = 0.f;
    __syncthreads();

    int gid = blockIdx.x * 256 + tid;
    int d = gid & 15;
    int j = (gid >> 4) % 10;
    int i = gid / 160;
    if (i < NI) {
        const float4* Wp = (const float4*)(W + (((size_t)j * NI + i) * 16 + d) * 8);
        float4 w0 = Wp[0], w1 = Wp[1];
        for (int b = 0; b < BATCH; b++) {
            const float4* up = (const float4*)(g_u + ((size_t)b * NI + i) * 8);
            float4 u0 = up[0], u1 = up[1];
            float acc = w0.x*u0.x + w0.y*u0.y + w0.z*u0.z + w0.w*u0.w
                      + w1.x*u1.x + w1.y*u1.y + w1.z*u1.z + w1.w*u1.w;
            g_uhatb[(((size_t)b * NI + i) * 10 + j) * 16 + d] = __float2bfloat16(acc);
            atomicAdd(&ssh[b * 160 + j * 16 + d], acc);
        }
    }
    __syncthreads();
    for (int t = tid; t < 2560; t += 256)
        if (ssh[t] != 0.f) atomicAdd(&g_s[t], 0.1f * ssh[t]);
}

// ---------------- routing (rounds 2,3) ----------------
__global__ __launch_bounds__(256)
void routing_s_kernel() {
    __shared__ float Vsh[160];
    __shared__ float ssh[160];
    int tid = threadIdx.x;
    int b = blockIdx.y;
    if (tid < 160) { Vsh[tid] = g_V[b * 160 + tid]; ssh[tid] = 0.f; }
    __syncthreads();
    int d = tid & 15, il = tid >> 4;
    float accj[10];
    #pragma unroll
    for (int j = 0; j < 10; j++) accj[j] = 0.f;
    const int per = NI / 32;
    int i0 = blockIdx.x * per;
    for (int i = i0 + il; i < i0 + per; i += 16) {
        const __nv_bfloat16* uh = g_uhatb + (((size_t)b * NI + i) * 10) * 16 + d;
        float uv[10], e[10];
        float m = -1e30f;
        #pragma unroll
        for (int j = 0; j < 10; j++) {
            uv[j] = __bfloat162float(uh[j * 16]);
            float l = uv[j] * Vsh[j * 16 + d];
            e[j] = l;
            m = fmaxf(m, l);
        }
        float se = 0.f;
        #pragma unroll
        for (int j = 0; j < 10; j++) { e[j] = __expf(e[j] - m); se += e[j]; }
        float inv = 1.f / se;
        #pragma unroll
        for (int j = 0; j < 10; j++) accj[j] += e[j] * inv * uv[j];
    }
    #pragma unroll
    for (int j = 0; j < 10; j++) atomicAdd(&ssh[j * 16 + d], accj[j]);
    __syncthreads();
    if (tid < 160) atomicAdd(&g_s[b * 160 + tid], ssh[tid]);
}

__global__ void v_update_kernel(int last, float* __restrict__ dout) {
    __shared__ float s2sh[10];
    __shared__ float nrm[10];
    __shared__ int amax;
    int b = blockIdx.x, tid = threadIdx.x;
    int j = tid >> 4, d = tid & 15;
    if (tid < 10) s2sh[tid] = 0.f;
    __syncthreads();
    float sv = g_s[b * 160 + tid];
    atomicAdd(&s2sh[j], sv * sv);
    __syncthreads();
    float s2 = s2sh[j];
    float v = s2 / (1.f + s2) * sv * rsqrtf(s2 + EPSQ);
    if (!last) {
        g_V[b * 160 + tid] += v;
    } else {
        if (d == 0) nrm[j] = s2 / (1.f + s2) * sqrtf(s2) * rsqrtf(s2 + EPSQ);
        __syncthreads();
        if (tid == 0) {
            int bm = 0; float mx = nrm[0];
            for (int jj = 1; jj < 10; jj++)
                if (nrm[jj] > mx) { mx = nrm[jj]; bm = jj; }
            amax = bm;
        }
        if (d == 0) dout[b * 10 + j] = nrm[j];
        __syncthreads();
        g_masked[b * 160 + tid] = (j == amax) ? v : 0.f;
    }
}

// ---------------- decoder FC: 16 batches per block, transposed conflict-free smem ----------------
__global__ void fc_multi_kernel(const float* __restrict__ in, const float* __restrict__ W,
                                const float* __restrict__ bias, float* __restrict__ out,
                                int IN, int OUT, int act) {
    extern __shared__ float s_in[];   // [IN][16] transposed
    int tid = threadIdx.x;
    for (int t = tid; t < 16 * IN; t += blockDim.x) {
        int b = t / IN, k = t - b * IN;
        s_in[k * 16 + b] = in[t];
    }
    __syncthreads();
    int o = blockIdx.x * blockDim.x + tid;
    if (o >= OUT) return;
    float bv = bias[o];
    float acc[16];
    #pragma unroll
    for (int b = 0; b < 16; b++) acc[b] = bv;
    for (int k = 0; k < IN; k++) {
        float w = W[(size_t)k * OUT + o];
        const float* sk = &s_in[k * 16];
        #pragma unroll
        for (int b = 0; b < 16; b++) acc[b] += sk[b] * w;
    }
    #pragma unroll
    for (int b = 0; b < 16; b++) {
        float v = acc[b];
        if (act == 1) v = fmaxf(v, 0.f);
        else          v = 1.f / (1.f + __expf(-v));
        out[(size_t)b * OUT + o] = v;
    }
}

// ---------------- launch ----------------
extern "C" void kernel_launch(void* const* d_in, const int* in_sizes, int n_in,
                              void* d_out, int out_size) {
    const float* x   = (const float*)d_in[0];
    const float* c1w = (const float*)d_in[1];
    const float* c1b = (const float*)d_in[2];
    const float* c2w = (const float*)d_in[3];
    const float* c2b = (const float*)d_in[4];
    const float* pcw = (const float*)d_in[5];
    const float* pcb = (const float*)d_in[6];
    const float* Wc  = (const float*)d_in[7];
    const float* w1  = (const float*)d_in[8];
    const float* b1  = (const float*)d_in[9];
    const float* w2  = (const float*)d_in[10];
    const float* b2  = (const float*)d_in[11];
    const float* w3  = (const float*)d_in[12];
    const float* b3  = (const float*)d_in[13];
    float* dout = (float*)d_out;

    __nv_bfloat16 *p_c1b, *p_c2b, *p_w1b, *p_w2b, *p_wpb;
    float *p_part, *p_p, *p_s, *p_V, *p_masked, *p_d1, *p_d2;
    cudaGetSymbolAddress((void**)&p_c1b, g_c1b);
    cudaGetSymbolAddress((void**)&p_c2b, g_c2b);
    cudaGetSymbolAddress((void**)&p_part, g_part);
    cudaGetSymbolAddress((void**)&p_p,  g_p);
    cudaGetSymbolAddress((void**)&p_w1b, g_w1b);
    cudaGetSymbolAddress((void**)&p_w2b, g_w2b);
    cudaGetSymbolAddress((void**)&p_wpb, g_wpb);
    cudaGetSymbolAddress((void**)&p_s,  g_s);
    cudaGetSymbolAddress((void**)&p_V,  g_V);
    cudaGetSymbolAddress((void**)&p_masked, g_masked);
    cudaGetSymbolAddress((void**)&p_d1, g_d1);
    cudaGetSymbolAddress((void**)&p_d2, g_d2);

    auto conv2 = conv_mma_kernel<56, 56, 52, 52, 5, 1, 100, 2, 43264>;
    auto convp = conv_mma_kernel<52, 52, 22, 22, 9, 2, 324, 12, 7744>;
    cudaFuncSetAttribute(conv2, cudaFuncAttributeMaxDynamicSharedMemorySize, SMEM_CONV_TOTAL);
    cudaFuncSetAttribute(convp, cudaFuncAttributeMaxDynamicSharedMemorySize, SMEM_CONV_TOTAL);
    cudaFuncSetAttribute(conv1_mma_kernel, cudaFuncAttributeMaxDynamicSharedMemorySize, C1_SMEM);
    cudaFuncSetAttribute(fc_multi_kernel, cudaFuncAttributeMaxDynamicSharedMemorySize, 66560);

    transform_w1_kernel<<<(2 * 64 * 128 + 255) / 256, 256>>>(c1w, p_w1b);
    transform_w_kernel<<<(100 * 8192 + 255) / 256, 256>>>(c2w, p_w2b, 5, 5, 100);
    transform_w_kernel<<<(324 * 8192 + 255) / 256, 256>>>(pcw, p_wpb, 9, 9, 324);

    conv1_mma_kernel<<<392, 512, C1_SMEM>>>(x, p_w1b, c1b, p_c1b);

    conv2<<<dim3(338, 2, 2), 256, SMEM_CONV_TOTAL>>>(p_c1b, p_w2b, p_part);
    reduce2_kernel<<<(int)(((size_t)43264 * 128 + 255) / 256), 256>>>(p_part, c2b, p_c2b);

    convp<<<dim3(61, 2, 12), 256, SMEM_CONV_TOTAL>>>(p_c2b, p_wpb, p_part);
    reducep_kernel<<<(7744 * 64 + 255) / 256, 256>>>(p_part, pcb, p_p);

    squash_u_kernel<<<(BATCH * NI + 255) / 256, 256>>>();

    cudaMemsetAsync(p_V, 0, BATCH * 160 * sizeof(float));
    cudaMemsetAsync(p_s, 0, BATCH * 160 * sizeof(float));
    uhat_kernel<<<((size_t)NI * 160 + 255) / 256, 256>>>(Wc);
    v_update_kernel<<<16, 160>>>(0, dout);

    for (int r = 1; r < 3; r++) {
        cudaMemsetAsync(p_s, 0, BATCH * 160 * sizeof(float));
        routing_s_kernel<<<dim3(32, 16), 256>>>();
        v_update_kernel<<<16, 160>>>(r == 2 ? 1 : 0, dout);
    }

    fc_multi_kernel<<<2, 256, 16 * 160 * 4>>>(p_masked, w1, b1, p_d1, 160, 512, 1);
    fc_multi_kernel<<<4, 256, 16 * 512 * 4>>>(p_d1, w2, b2, p_d2, 512, 1024, 1);
    fc_multi_kernel<<<16, 256, 16 * 1024 * 4>>>(p_d2, w3, b3, dout + 160, 1024, 4096, 2);
}

// round 17
// speedup vs baseline: 1.5874x; 1.1910x over previous
#include <cuda_runtime.h>
#include <cuda_bf16.h>
#include <cstdint>

#define EPSQ 1e-8f
static const int BATCH = 16;
static const int NI = 15488;

// ---------------- scratch ----------------
__device__ __nv_bfloat16 g_c1b[(size_t)50176 * 256];
__device__ __nv_bfloat16 g_c2b[(size_t)43264 * 256];
__device__ float g_part[(size_t)12 * 7744 * 256];
__device__ float g_p [(size_t)16 * 256 * 22 * 22];
__device__ float g_u [(size_t)16 * 15488 * 8];
__device__ __nv_bfloat16 g_uhatb[(size_t)16 * 15488 * 10 * 16];
__device__ __nv_bfloat16 g_w1b[(size_t)2 * 16384];
__device__ __nv_bfloat16 g_w2b[(size_t)200 * 8192];
__device__ __nv_bfloat16 g_wpb[(size_t)648 * 8192];
__device__ float g_s[16 * 160];
__device__ float g_V[16 * 160];
__device__ float g_masked[16 * 160];
__device__ float g_d1[16 * 512];
__device__ float g_d2[16 * 1024];

// ---------------- helpers ----------------
__device__ __forceinline__ uint32_t smem_to_u32(const void* p) {
    uint32_t a;
    asm("{ .reg .u64 t; cvta.to.shared.u64 t, %1; cvt.u32.u64 %0, t; }" : "=r"(a) : "l"(p));
    return a;
}
__device__ __forceinline__ void ldsm_x4(uint32_t& r0, uint32_t& r1, uint32_t& r2, uint32_t& r3, uint32_t addr) {
    asm volatile("ldmatrix.sync.aligned.m8n8.x4.shared.b16 {%0,%1,%2,%3}, [%4];"
                 : "=r"(r0), "=r"(r1), "=r"(r2), "=r"(r3) : "r"(addr));
}
__device__ __forceinline__ void ldsm_x4_t(uint32_t& r0, uint32_t& r1, uint32_t& r2, uint32_t& r3, uint32_t addr) {
    asm volatile("ldmatrix.sync.aligned.m8n8.x4.trans.shared.b16 {%0,%1,%2,%3}, [%4];"
                 : "=r"(r0), "=r"(r1), "=r"(r2), "=r"(r3) : "r"(addr));
}
__device__ __forceinline__ void mma16816(float* c, const uint32_t* a, const uint32_t* b) {
    asm volatile("mma.sync.aligned.m16n8k16.row.col.f32.bf16.bf16.f32 "
                 "{%0,%1,%2,%3}, {%4,%5,%6,%7}, {%8,%9}, {%0,%1,%2,%3};"
                 : "+f"(c[0]), "+f"(c[1]), "+f"(c[2]), "+f"(c[3])
                 : "r"(a[0]), "r"(a[1]), "r"(a[2]), "r"(a[3]), "r"(b[0]), "r"(b[1]));
}
#define CP_ASYNC16(dst, src, sz) \
    asm volatile("cp.async.cg.shared.global [%0], [%1], 16, %2;" :: "r"(dst), "l"(src), "r"(sz))
#define CP_COMMIT() asm volatile("cp.async.commit_group;" ::: "memory")
#define CP_WAIT(n)  asm volatile("cp.async.wait_group %0;" :: "n"(n) : "memory")

__device__ __forceinline__ uint32_t bf_pack(float a, float b) {
    return ((uint32_t)__bfloat16_as_ushort(__float2bfloat16(b)) << 16)
         | __bfloat16_as_ushort(__float2bfloat16(a));
}

// ---------------- weight transforms ----------------
__global__ void transform_w_kernel(const float* __restrict__ w,
                                   __nv_bfloat16* __restrict__ wb,
                                   int KH, int KW, int NCHUNK) {
    int idx = blockIdx.x * 256 + threadIdx.x;
    int total = NCHUNK * 2 * 64 * 64;
    if (idx >= total) return;
    int np = idx & 63;
    int k  = (idx >> 6) & 63;
    int ntile = (idx >> 12) & 1;
    int chunk = idx >> 13;
    int kyx = chunk >> 2;
    int ic = (chunk & 3) * 64 + k;
    int ky = kyx / KW, kx = kyx % KW;
    int oc = ntile * 128 + np * 2;
    size_t KHW = (size_t)KH * KW;
    size_t wi = (((size_t)oc * 256 + ic) * KH + ky) * KW + kx;
    uint32_t pk = bf_pack(w[wi], w[wi + 256 * KHW]);
    int off = k * 256 + np * 4;
    int sw = off ^ ((k & 7) << 4);
    *(uint32_t*)((char*)wb + (size_t)(chunk * 2 + ntile) * 16384 + sw) = pk;
}

__global__ void transform_w1_kernel(const float* __restrict__ w,
                                    __nv_bfloat16* __restrict__ wb) {
    int idx = blockIdx.x * 256 + threadIdx.x;
    if (idx >= 2 * 64 * 128) return;
    int np = idx & 127;
    int k  = (idx >> 7) & 63;
    int chunk = idx >> 13;
    int kk = chunk * 64 + k;
    int oc = np * 2;
    float f0 = (kk < 81) ? w[(size_t)oc * 81 + kk] : 0.f;
    float f1 = (kk < 81) ? w[(size_t)(oc + 1) * 81 + kk] : 0.f;
    int off = k * 512 + np * 4;
    int sw = off ^ ((k & 7) << 4);
    *(uint32_t*)((char*)wb + (size_t)chunk * 32768 + sw) = bf_pack(f0, f1);
}

// ---------------- conv1 via HMMA ----------------
#define C1_STG 49152
#define C1_SMEM (2 * C1_STG)

__global__ __launch_bounds__(512, 1)
void conv1_mma_kernel(const float* __restrict__ x,
                      const __nv_bfloat16* __restrict__ wb,
                      const float* __restrict__ bias,
                      __nv_bfloat16* __restrict__ ob16) {
    extern __shared__ char smem[];
    const uint32_t sb = smem_to_u32(smem);
    const int tid = threadIdx.x;
    const int wid = tid >> 5, lid = tid & 31;
    const int tile = blockIdx.x;

    const int r = tid >> 2, sp = tid & 3;
    const int p_mine = tile * 128 + r;
    const bool pvalid = p_mine < 50176;
    int pb = 0, pr = 0, pcx = 0;
    if (pvalid) {
        pb = p_mine / 3136;
        int rem = p_mine - pb * 3136;
        pr = rem / 56;
        pcx = rem - pr * 56;
    }

    const int wm = wid >> 2, wn = wid & 3;
    const int lane15 = lid & 15, lane16 = lid >> 4;
    const int gid = lid >> 2, tig = lid & 3;

    float acc[2][8][4];
    #pragma unroll
    for (int ma = 0; ma < 2; ma++)
        #pragma unroll
        for (int na = 0; na < 8; na++)
            #pragma unroll
            for (int q = 0; q < 4; q++) acc[ma][na][q] = 0.f;

    #pragma unroll
    for (int c = 0; c < 2; c++) {
        uint32_t s0 = sb + c * C1_STG;
        const char* bsrc = (const char*)(wb + (size_t)c * 16384);
        #pragma unroll
        for (int i = 0; i < 4; i++) {
            uint32_t u = (tid + i * 512) * 16;
            CP_ASYNC16(s0 + 16384 + u, bsrc + u, 16);
        }
        const float* xb = x + (size_t)pb * 4096;
        #pragma unroll
        for (int t = 0; t < 8; t++) {
            int k0 = c * 64 + sp * 16 + 2 * t;
            float v0 = 0.f, v1 = 0.f;
            if (pvalid && k0 < 81) {
                int ky = k0 / 9, kx = k0 - 9 * ky;
                v0 = xb[(pr + ky) * 64 + pcx + kx];
            }
            if (pvalid && k0 + 1 < 81) {
                int ky = (k0 + 1) / 9, kx = (k0 + 1) - 9 * ky;
                v1 = xb[(pr + ky) * 64 + pcx + kx];
            }
            uint32_t off = r * 128 + (sp * 16 + 2 * t) * 2;
            uint32_t sw = off ^ ((r & 7) << 4);
            *(uint32_t*)(smem + c * C1_STG + sw) = bf_pack(v0, v1);
        }
    }
    CP_COMMIT();
    CP_WAIT(0);
    __syncthreads();

    #pragma unroll
    for (int c = 0; c < 2; c++) {
        const uint32_t s0 = sb + c * C1_STG;
        #pragma unroll
        for (int ks = 0; ks < 4; ks++) {
            uint32_t B[8][2];
            const int brow = ks * 16 + lane15;
            #pragma unroll
            for (int q = 0; q < 4; q++) {
                uint32_t off = brow * 512 + wn * 128 + q * 32 + lane16 * 16;
                uint32_t sw = off ^ ((brow & 7) << 4);
                ldsm_x4_t(B[2*q][0], B[2*q][1], B[2*q+1][0], B[2*q+1][1], s0 + 16384 + sw);
            }
            #pragma unroll
            for (int ma = 0; ma < 2; ma++) {
                const int arow = wm * 32 + ma * 16 + lane15;
                uint32_t offA = arow * 128 + ks * 32 + lane16 * 16;
                uint32_t swA = offA ^ ((arow & 7) << 4);
                uint32_t a[4];
                ldsm_x4(a[0], a[1], a[2], a[3], s0 + swA);
                #pragma unroll
                for (int na = 0; na < 8; na++) mma16816(acc[ma][na], a, B[na]);
            }
        }
    }

    #pragma unroll
    for (int ma = 0; ma < 2; ma++)
        #pragma unroll
        for (int h = 0; h < 2; h++) {
            int p = tile * 128 + wm * 32 + ma * 16 + h * 8 + gid;
            if (p >= 50176) continue;
            __nv_bfloat16* op = ob16 + (size_t)p * 256;
            #pragma unroll
            for (int na = 0; na < 8; na++) {
                int oc = wn * 64 + na * 8 + tig * 2;
                float v0 = fmaxf(acc[ma][na][h * 2 + 0] + bias[oc],     0.f);
                float v1 = fmaxf(acc[ma][na][h * 2 + 1] + bias[oc + 1], 0.f);
                *(uint32_t*)(op + oc) = bf_pack(v0, v1);
            }
        }
}

// ---------------- conv2/pc: 256 thr, 128x128 tile, 2 CTAs/SM, 3-stage, fp32 partials ----------------
#define STG 32768
#define SMEM_CONV_TOTAL (3 * STG)

template<int IH, int IW, int OH, int OW, int KW, int STRIDE, int NCHUNK, int KSPLIT, int NPOS>
__global__ __launch_bounds__(256, 2)
void conv_mma_kernel(const __nv_bfloat16* __restrict__ inb,
                     const __nv_bfloat16* __restrict__ wb,
                     float* __restrict__ part) {
    extern __shared__ char smem[];
    const uint32_t sb = smem_to_u32(smem);
    const int tid = threadIdx.x;
    const int wid = tid >> 5, lid = tid & 31;
    const int tile = blockIdx.x, ntile = blockIdx.y;

    const int r = tid >> 1, sp = tid & 1;
    const int p_mine = tile * 128 + r;
    const bool pvalid = p_mine < NPOS;
    int pb = 0, pr = 0, pcx = 0;
    if (pvalid) {
        pb = p_mine / (OH * OW);
        int rem = p_mine - pb * (OH * OW);
        pr = rem / OW;
        pcx = rem - pr * OW;
    }
    const int asz = pvalid ? 16 : 0;

    const int wm = wid >> 1, wn = wid & 1;
    const int lane15 = lid & 15, lane16 = lid >> 4;
    const int gid = lid >> 2, tig = lid & 3;

    float acc[2][8][4];
    #pragma unroll
    for (int ma = 0; ma < 2; ma++)
        #pragma unroll
        for (int na = 0; na < 8; na++)
            #pragma unroll
            for (int q = 0; q < 4; q++) acc[ma][na][q] = 0.f;

    const int NC = NCHUNK / KSPLIT;
    const int coff = blockIdx.z * NC;

    auto fill = [&](int stage, int chunk) {
        uint32_t s0 = sb + stage * STG;
        const char* bsrc = (const char*)(wb + (size_t)(chunk * 2 + ntile) * 8192);
        #pragma unroll
        for (int i = 0; i < 4; i++) {
            uint32_t u = (tid + i * 256) * 16;
            CP_ASYNC16(s0 + 16384 + u, bsrc + u, 16);
        }
        const int kyx = chunk >> 2;
        const int ic0 = (chunk & 3) * 64;
        const int ky = kyx / KW, kx = kyx % KW;
        size_t srcbase = 0;
        if (pvalid) {
            int iy = pr * STRIDE + ky, ix = pcx * STRIDE + kx;
            srcbase = (((size_t)pb * IH + iy) * IW + ix) * 256 + ic0;
        }
        #pragma unroll
        for (int q = 0; q < 4; q++) {
            int seg = sp * 4 + q;
            uint32_t off = r * 128 + seg * 16;
            uint32_t sw = off ^ ((r & 7) << 4);
            CP_ASYNC16(s0 + sw, (const char*)(inb + srcbase + seg * 8), asz);
        }
    };

    fill(0, coff);              CP_COMMIT();
    if (NC > 1) { fill(1, coff + 1); CP_COMMIT(); }

    int st = 0;
    for (int i = 0; i < NC; ++i) {
        if (i + 1 < NC) { CP_WAIT(1); } else { CP_WAIT(0); }
        __syncthreads();

        const uint32_t s0 = sb + st * STG;
        #pragma unroll
        for (int ks = 0; ks < 4; ks++) {
            uint32_t B[8][2];
            const int brow = ks * 16 + lane15;
            #pragma unroll
            for (int q = 0; q < 4; q++) {
                uint32_t off = brow * 256 + wn * 128 + q * 32 + lane16 * 16;
                uint32_t sw = off ^ ((brow & 7) << 4);
                ldsm_x4_t(B[2*q][0], B[2*q][1], B[2*q+1][0], B[2*q+1][1], s0 + 16384 + sw);
            }
            #pragma unroll
            for (int ma = 0; ma < 2; ma++) {
                const int arow = wm * 32 + ma * 16 + lane15;
                uint32_t offA = arow * 128 + ks * 32 + lane16 * 16;
                uint32_t swA = offA ^ ((arow & 7) << 4);
                uint32_t a[4];
                ldsm_x4(a[0], a[1], a[2], a[3], s0 + swA);
                #pragma unroll
                for (int na = 0; na < 8; na++) mma16816(acc[ma][na], a, B[na]);
            }
            if (ks == 0 && i + 2 < NC) { fill((st + 2) % 3, coff + i + 2); CP_COMMIT(); }
        }
        st = (st + 1) % 3;
    }

    float* op0 = part + (size_t)blockIdx.z * NPOS * 256;
    #pragma unroll
    for (int ma = 0; ma < 2; ma++)
        #pragma unroll
        for (int h = 0; h < 2; h++) {
            int p = tile * 128 + wm * 32 + ma * 16 + h * 8 + gid;
            if (p >= NPOS) continue;
            float* op = op0 + (size_t)p * 256 + ntile * 128 + wn * 64 + tig * 2;
            #pragma unroll
            for (int na = 0; na < 8; na++)
                *(float2*)(op + na * 8) = make_float2(acc[ma][na][h * 2], acc[ma][na][h * 2 + 1]);
        }
}

// ---------------- reduce conv2 (2-way) -> bias+relu -> bf16 NHWC ----------------
__global__ void reduce2_kernel(const float* __restrict__ part, const float* __restrict__ bias,
                               __nv_bfloat16* __restrict__ ob16) {
    size_t gid = (size_t)blockIdx.x * 256 + threadIdx.x;
    if (gid >= (size_t)43264 * 128) return;
    int p = (int)(gid >> 7);
    int oc = ((int)gid & 127) * 2;
    const float* p0 = part + (size_t)p * 256 + oc;
    const size_t half = (size_t)43264 * 256;
    float v0 = fmaxf(p0[0] + p0[half]     + bias[oc],     0.f);
    float v1 = fmaxf(p0[1] + p0[half + 1] + bias[oc + 1], 0.f);
    *(uint32_t*)(ob16 + (size_t)p * 256 + oc) = bf_pack(v0, v1);
}

// ---------------- reduce pc partials (12-way) -> bias -> fp32 NCHW ----------------
__global__ void reducep_kernel(const float* __restrict__ part, const float* __restrict__ bias,
                               float* __restrict__ out) {
    int gid = blockIdx.x * 256 + threadIdx.x;
    if (gid >= 7744 * 64) return;
    int p = gid >> 6, oc = (gid & 63) * 4;
    const size_t seg = (size_t)7744 * 256;
    const float* p0 = part + (size_t)p * 256 + oc;
    float4 v = *(const float4*)p0;
    #pragma unroll
    for (int k = 1; k < 12; k++) {
        float4 t = *(const float4*)(p0 + k * seg);
        v.x += t.x; v.y += t.y; v.z += t.z; v.w += t.w;
    }
    const float4 bv = *(const float4*)(bias + oc);
    v.x += bv.x; v.y += bv.y; v.z += bv.z; v.w += bv.w;
    int b = p / 484;
    int rem = p - b * 484;
    int rr = rem / 22, cx = rem - rr * 22;
    size_t base = (((size_t)b * 256 + oc) * 22 + rr) * 22 + cx;
    out[base] = v.x; out[base + 484] = v.y;
    out[base + 2 * 484] = v.z; out[base + 3 * 484] = v.w;
}

// ---------------- squash ----------------
__global__ void squash_u_kernel() {
    int cap = blockIdx.x * 256 + threadIdx.x;
    if (cap >= BATCH * NI) return;
    const float4* pp = (const float4*)(g_p + (size_t)cap * 8);
    float4 a = pp[0], c = pp[1];
    float s2 = a.x*a.x + a.y*a.y + a.z*a.z + a.w*a.w + c.x*c.x + c.y*c.y + c.z*c.z + c.w*c.w;
    float f = s2 / (1.f + s2) * rsqrtf(s2 + EPSQ);
    a.x *= f; a.y *= f; a.z *= f; a.w *= f;
    c.x *= f; c.y *= f; c.z *= f; c.w *= f;
    float4* uo = (float4*)(g_u + (size_t)cap * 8);
    uo[0] = a; uo[1] = c;
}

// ---------------- u_hat (bf16) + fused round-1 s ----------------
__global__ __launch_bounds__(256)
void uhat_kernel(const float* __restrict__ W) {
    __shared__ float ssh[2560];
    int tid = threadIdx.x;
    for (int t = tid; t < 2560; t += 256) ssh[t] = 0.f;
    __syncthreads();

    int gid = blockIdx.x * 256 + tid;
    int d = gid & 15;
    int j = (gid >> 4) % 10;
    int i = gid / 160;
    if (i < NI) {
        const float4* Wp = (const float4*)(W + (((size_t)j * NI + i) * 16 + d) * 8);
        float4 w0 = Wp[0], w1 = Wp[1];
        for (int b = 0; b < BATCH; b++) {
            const float4* up = (const float4*)(g_u + ((size_t)b * NI + i) * 8);
            float4 u0 = up[0], u1 = up[1];
            float acc = w0.x*u0.x + w0.y*u0.y + w0.z*u0.z + w0.w*u0.w
                      + w1.x*u1.x + w1.y*u1.y + w1.z*u1.z + w1.w*u1.w;
            g_uhatb[(((size_t)b * NI + i) * 10 + j) * 16 + d] = __float2bfloat16(acc);
            atomicAdd(&ssh[b * 160 + j * 16 + d], acc);
        }
    }
    __syncthreads();
    for (int t = tid; t < 2560; t += 256)
        if (ssh[t] != 0.f) atomicAdd(&g_s[t], 0.1f * ssh[t]);
}

// ---------------- routing (rounds 2,3) ----------------
__global__ __launch_bounds__(256)
void routing_s_kernel() {
    __shared__ float Vsh[160];
    __shared__ float ssh[160];
    int tid = threadIdx.x;
    int b = blockIdx.y;
    if (tid < 160) { Vsh[tid] = g_V[b * 160 + tid]; ssh[tid] = 0.f; }
    __syncthreads();
    int d = tid & 15, il = tid >> 4;
    float accj[10];
    #pragma unroll
    for (int j = 0; j < 10; j++) accj[j] = 0.f;
    const int per = NI / 32;
    int i0 = blockIdx.x * per;
    for (int i = i0 + il; i < i0 + per; i += 16) {
        const __nv_bfloat16* uh = g_uhatb + (((size_t)b * NI + i) * 10) * 16 + d;
        float uv[10], e[10];
        float m = -1e30f;
        #pragma unroll
        for (int j = 0; j < 10; j++) {
            uv[j] = __bfloat162float(uh[j * 16]);
            float l = uv[j] * Vsh[j * 16 + d];
            e[j] = l;
            m = fmaxf(m, l);
        }
        float se = 0.f;
        #pragma unroll
        for (int j = 0; j < 10; j++) { e[j] = __expf(e[j] - m); se += e[j]; }
        float inv = 1.f / se;
        #pragma unroll
        for (int j = 0; j < 10; j++) accj[j] += e[j] * inv * uv[j];
    }
    #pragma unroll
    for (int j = 0; j < 10; j++) atomicAdd(&ssh[j * 16 + d], accj[j]);
    __syncthreads();
    if (tid < 160) atomicAdd(&g_s[b * 160 + tid], ssh[tid]);
}

// ---------------- v update: mode 0=first (V=v), 1=mid (V+=v), 2=last (outputs) ----------------
// Also zeroes g_s for the next round after consuming it (removes memset launches).
__global__ void v_update_kernel(int mode, float* __restrict__ dout) {
    __shared__ float s2sh[10];
    __shared__ float nrm[10];
    __shared__ int amax;
    int b = blockIdx.x, tid = threadIdx.x;
    int j = tid >> 4, d = tid & 15;
    if (tid < 10) s2sh[tid] = 0.f;
    __syncthreads();
    float sv = g_s[b * 160 + tid];
    g_s[b * 160 + tid] = 0.f;   // ready for next round's atomics
    atomicAdd(&s2sh[j], sv * sv);
    __syncthreads();
    float s2 = s2sh[j];
    float v = s2 / (1.f + s2) * sv * rsqrtf(s2 + EPSQ);
    if (mode == 0) {
        g_V[b * 160 + tid] = v;
    } else if (mode == 1) {
        g_V[b * 160 + tid] += v;
    } else {
        if (d == 0) nrm[j] = s2 / (1.f + s2) * sqrtf(s2) * rsqrtf(s2 + EPSQ);
        __syncthreads();
        if (tid == 0) {
            int bm = 0; float mx = nrm[0];
            for (int jj = 1; jj < 10; jj++)
                if (nrm[jj] > mx) { mx = nrm[jj]; bm = jj; }
            amax = bm;
        }
        if (d == 0) dout[b * 10 + j] = nrm[j];
        __syncthreads();
        g_masked[b * 160 + tid] = (j == amax) ? v : 0.f;
    }
}

// ---------------- decoder FC (R14 per-output version; W is L2-resident) ----------------
__global__ void fc_kernel(const float* __restrict__ in, const float* __restrict__ W,
                          const float* __restrict__ bias, float* __restrict__ out,
                          int IN, int OUT, int act) {
    int gid = blockIdx.x * blockDim.x + threadIdx.x;
    if (gid >= BATCH * OUT) return;
    int o = gid % OUT, b = gid / OUT;
    const float* ip = in + (size_t)b * IN;
    float acc = bias[o];
    for (int k = 0; k < IN; k++) acc += ip[k] * W[(size_t)k * OUT + o];
    if (act == 1) acc = fmaxf(acc, 0.f);
    else          acc = 1.f / (1.f + __expf(-acc));
    out[gid] = acc;
}

// ---------------- launch ----------------
extern "C" void kernel_launch(void* const* d_in, const int* in_sizes, int n_in,
                              void* d_out, int out_size) {
    const float* x   = (const float*)d_in[0];
    const float* c1w = (const float*)d_in[1];
    const float* c1b = (const float*)d_in[2];
    const float* c2w = (const float*)d_in[3];
    const float* c2b = (const float*)d_in[4];
    const float* pcw = (const float*)d_in[5];
    const float* pcb = (const float*)d_in[6];
    const float* Wc  = (const float*)d_in[7];
    const float* w1  = (const float*)d_in[8];
    const float* b1  = (const float*)d_in[9];
    const float* w2  = (const float*)d_in[10];
    const float* b2  = (const float*)d_in[11];
    const float* w3  = (const float*)d_in[12];
    const float* b3  = (const float*)d_in[13];
    float* dout = (float*)d_out;

    __nv_bfloat16 *p_c1b, *p_c2b, *p_w1b, *p_w2b, *p_wpb;
    float *p_part, *p_p, *p_s, *p_V, *p_masked, *p_d1, *p_d2;
    cudaGetSymbolAddress((void**)&p_c1b, g_c1b);
    cudaGetSymbolAddress((void**)&p_c2b, g_c2b);
    cudaGetSymbolAddress((void**)&p_part, g_part);
    cudaGetSymbolAddress((void**)&p_p,  g_p);
    cudaGetSymbolAddress((void**)&p_w1b, g_w1b);
    cudaGetSymbolAddress((void**)&p_w2b, g_w2b);
    cudaGetSymbolAddress((void**)&p_wpb, g_wpb);
    cudaGetSymbolAddress((void**)&p_s,  g_s);
    cudaGetSymbolAddress((void**)&p_V,  g_V);
    cudaGetSymbolAddress((void**)&p_masked, g_masked);
    cudaGetSymbolAddress((void**)&p_d1, g_d1);
    cudaGetSymbolAddress((void**)&p_d2, g_d2);

    auto conv2 = conv_mma_kernel<56, 56, 52, 52, 5, 1, 100, 2, 43264>;
    auto convp = conv_mma_kernel<52, 52, 22, 22, 9, 2, 324, 12, 7744>;
    cudaFuncSetAttribute(conv2, cudaFuncAttributeMaxDynamicSharedMemorySize, SMEM_CONV_TOTAL);
    cudaFuncSetAttribute(convp, cudaFuncAttributeMaxDynamicSharedMemorySize, SMEM_CONV_TOTAL);
    cudaFuncSetAttribute(conv1_mma_kernel, cudaFuncAttributeMaxDynamicSharedMemorySize, C1_SMEM);

    transform_w1_kernel<<<(2 * 64 * 128 + 255) / 256, 256>>>(c1w, p_w1b);
    transform_w_kernel<<<(100 * 8192 + 255) / 256, 256>>>(c2w, p_w2b, 5, 5, 100);
    transform_w_kernel<<<(324 * 8192 + 255) / 256, 256>>>(pcw, p_wpb, 9, 9, 324);

    conv1_mma_kernel<<<392, 512, C1_SMEM>>>(x, p_w1b, c1b, p_c1b);

    conv2<<<dim3(338, 2, 2), 256, SMEM_CONV_TOTAL>>>(p_c1b, p_w2b, p_part);
    reduce2_kernel<<<(int)(((size_t)43264 * 128 + 255) / 256), 256>>>(p_part, c2b, p_c2b);

    convp<<<dim3(61, 2, 12), 256, SMEM_CONV_TOTAL>>>(p_c2b, p_wpb, p_part);
    reducep_kernel<<<(7744 * 64 + 255) / 256, 256>>>(p_part, pcb, p_p);

    squash_u_kernel<<<(BATCH * NI + 255) / 256, 256>>>();

    // routing: round 1 fused into uhat (c = 1/10 uniform); g_s zeroed once here,
    // then v_update re-zeroes it after each consumption.
    cudaMemsetAsync(p_s, 0, BATCH * 160 * sizeof(float));
    uhat_kernel<<<((size_t)NI * 160 + 255) / 256, 256>>>(Wc);
    v_update_kernel<<<16, 160>>>(0, dout);

    routing_s_kernel<<<dim3(32, 16), 256>>>();
    v_update_kernel<<<16, 160>>>(1, dout);

    routing_s_kernel<<<dim3(32, 16), 256>>>();
    v_update_kernel<<<16, 160>>>(2, dout);

    fc_kernel<<<(BATCH * 512 + 255) / 256, 256>>>(p_masked, w1, b1, p_d1, 160, 512, 1);
    fc_kernel<<<(BATCH * 1024 + 255) / 256, 256>>>(p_d1, w2, b2, p_d2, 512, 1024, 1);
    fc_kernel<<<(BATCH * 4096 + 255) / 256, 256>>>(p_d2, w3, b3, dout + 160, 1024, 4096, 2);
}